// round 16
// baseline (speedup 1.0000x reference)
#include <cuda_runtime.h>
#include <math.h>
#include <stdint.h>

// Flow_49546742727298: CNF Euler, exact divergence via analytic trace.
// R16: R15 fp16-MMA zero-relayout kernel at 4 CTAs/SM:
//      launch_bounds(128,4) (128-reg cap), grid=592, cj re-read from smem
//      inside the loop (saves 16 regs to make the cap without spill).

#define THREADS 128
#define NSTEPS  2
#define GRID    (4 * 148)

__device__ __forceinline__ uint32_t pack_f16x2(float lo, float hi) {
    uint32_t d; asm("cvt.rn.f16x2.f32 %0, %1, %2;" : "=r"(d) : "f"(hi), "f"(lo)); return d;
}
__device__ __forceinline__ float fast_tanh(float x) {
    float y; asm("tanh.approx.f32 %0, %1;" : "=f"(y) : "f"(x)); return y;
}
__device__ __forceinline__ void mma_f16(float c[4], const uint32_t a[4],
                                        const uint32_t b0, const uint32_t b1) {
    asm("mma.sync.aligned.m16n8k16.row.col.f32.f16.f16.f32 "
        "{%0,%1,%2,%3}, {%4,%5,%6,%7}, {%8,%9}, {%0,%1,%2,%3};"
        : "+f"(c[0]), "+f"(c[1]), "+f"(c[2]), "+f"(c[3])
        : "r"(a[0]), "r"(a[1]), "r"(a[2]), "r"(a[3]), "r"(b0), "r"(b1));
}

__global__ void __launch_bounds__(THREADS, 4)
flow_kernel(const float* __restrict__ x0,
            const float* __restrict__ W1,
            const float* __restrict__ b1,
            const float* __restrict__ W2,
            const float* __restrict__ b2,
            float* __restrict__ out,
            int batch)
{
    __shared__ float sbias[2][64];   // [s][j]: b1[j] + t_s*wt[j]
    __shared__ float scj[64];        // c_j
    __shared__ __align__(8) float sb2s[16];

    const int tid  = threadIdx.x;
    const int lane = tid & 31;
    const int warp = tid >> 5;
    const int g    = lane >> 2;
    const int tg   = lane & 3;

    if (tid < 64) {
        const int j = tid;
        float c = 0.f;
        #pragma unroll
        for (int i = 0; i < 16; i++)
            c += W1[i * 64 + j] * W2[j * 16 + i];
        float bb = b1[j];
        float wt = W1[16 * 64 + j];
        scj[j] = c;
        sbias[0][j] = bb;
        sbias[1][j] = fmaf(0.5f, wt, bb);
    } else if (tid < 80) {
        sb2s[tid - 64] = b2[tid - 64];
    }
    __syncthreads();

    float csum;
    {
        float cpart = scj[lane] + scj[lane + 32];
        #pragma unroll
        for (int d = 16; d >= 1; d >>= 1)
            cpart += __shfl_xor_sync(0xffffffffu, cpart, d);
        csum = cpart;
    }

    // ---- persistent fp16 weight B-fragments (32 regs total) ----
    uint32_t w1f[8][2];
    #pragma unroll
    for (int nt = 0; nt < 8; nt++) {
        int col = 8 * nt + g;
        w1f[nt][0] = pack_f16x2(W1[(2 * tg)     * 64 + col], W1[(2 * tg + 1) * 64 + col]);
        w1f[nt][1] = pack_f16x2(W1[(2 * tg + 8) * 64 + col], W1[(2 * tg + 9) * 64 + col]);
    }
    uint32_t w2f[4][2][2];
    #pragma unroll
    for (int kt = 0; kt < 4; kt++)
        #pragma unroll
        for (int nt = 0; nt < 2; nt++) {
            int col = 8 * nt + g;
            int k0 = 16 * kt + 2 * tg;
            w2f[kt][nt][0] = pack_f16x2(W2[k0       * 16 + col], W2[(k0 + 1) * 16 + col]);
            w2f[kt][nt][1] = pack_f16x2(W2[(k0 + 8) * 16 + col], W2[(k0 + 9) * 16 + col]);
        }

    const float dt = 0.5f;
    const int gwarp  = blockIdx.x * 4 + warp;
    const int nwarps = GRID * 4;
    const int ntiles = batch >> 4;

    for (int wt = gwarp; wt < ntiles; wt += nwarps) {
        const int row0 = wt << 4;

        float xe[2][4];
        #pragma unroll
        for (int nt = 0; nt < 2; nt++) {
            float2 lo = *(const float2*)&x0[(size_t)(row0 + g)     * 16 + 8 * nt + 2 * tg];
            float2 hi = *(const float2*)&x0[(size_t)(row0 + g + 8) * 16 + 8 * nt + 2 * tg];
            xe[nt][0] = lo.x; xe[nt][1] = lo.y;
            xe[nt][2] = hi.x; xe[nt][3] = hi.y;
        }

        float logq0 = 0.f, logq1 = 0.f;

        #pragma unroll
        for (int s = 0; s < NSTEPS; s++) {
            uint32_t xa[4];
            xa[0] = pack_f16x2(xe[0][0], xe[0][1]);
            xa[1] = pack_f16x2(xe[0][2], xe[0][3]);
            xa[2] = pack_f16x2(xe[1][0], xe[1][1]);
            xa[3] = pack_f16x2(xe[1][2], xe[1][3]);

            // GEMM1: h = x @ W1 + bse
            float h[8][4];
            #pragma unroll
            for (int nt = 0; nt < 8; nt++) {
                float2 bb = *(const float2*)&sbias[s][8 * nt + 2 * tg];
                h[nt][0] = bb.x; h[nt][1] = bb.y;
                h[nt][2] = bb.x; h[nt][3] = bb.y;
                mma_f16(h[nt], xa, w1f[nt][0], w1f[nt][1]);
            }

            // tanh + divergence partials (cj from smem broadcast, saves regs)
            float d0 = 0.f, d1 = 0.f;
            #pragma unroll
            for (int nt = 0; nt < 8; nt++) {
                h[nt][0] = fast_tanh(h[nt][0]);
                h[nt][1] = fast_tanh(h[nt][1]);
                h[nt][2] = fast_tanh(h[nt][2]);
                h[nt][3] = fast_tanh(h[nt][3]);
                float2 cc = *(const float2*)&scj[8 * nt + 2 * tg];
                d0 = fmaf(h[nt][0] * h[nt][0], cc.x, d0);
                d0 = fmaf(h[nt][1] * h[nt][1], cc.y, d0);
                d1 = fmaf(h[nt][2] * h[nt][2], cc.x, d1);
                d1 = fmaf(h[nt][3] * h[nt][3], cc.y, d1);
            }
            d0 += __shfl_xor_sync(0xffffffffu, d0, 1);
            d0 += __shfl_xor_sync(0xffffffffu, d0, 2);
            d1 += __shfl_xor_sync(0xffffffffu, d1, 1);
            d1 += __shfl_xor_sync(0xffffffffu, d1, 2);
            logq0 -= dt * (csum - d0);
            logq1 -= dt * (csum - d1);

            // h C-frags -> GEMM2 A-frags: pure pack
            uint32_t ha[4][4];
            #pragma unroll
            for (int kt = 0; kt < 4; kt++) {
                ha[kt][0] = pack_f16x2(h[2 * kt][0],     h[2 * kt][1]);
                ha[kt][1] = pack_f16x2(h[2 * kt][2],     h[2 * kt][3]);
                ha[kt][2] = pack_f16x2(h[2 * kt + 1][0], h[2 * kt + 1][1]);
                ha[kt][3] = pack_f16x2(h[2 * kt + 1][2], h[2 * kt + 1][3]);
            }

            // GEMM2: v = h @ W2 + b2
            float v[2][4];
            #pragma unroll
            for (int nt = 0; nt < 2; nt++) {
                float2 bb = *(const float2*)&sb2s[8 * nt + 2 * tg];
                float va[4] = {bb.x, bb.y, bb.x, bb.y};
                float vb[4] = {0.f, 0.f, 0.f, 0.f};
                mma_f16(va, ha[0], w2f[0][nt][0], w2f[0][nt][1]);
                mma_f16(vb, ha[1], w2f[1][nt][0], w2f[1][nt][1]);
                mma_f16(va, ha[2], w2f[2][nt][0], w2f[2][nt][1]);
                mma_f16(vb, ha[3], w2f[3][nt][0], w2f[3][nt][1]);
                #pragma unroll
                for (int i = 0; i < 4; i++) v[nt][i] = va[i] + vb[i];
            }

            // direct exact-fp32 x update (v C-frag == x layout)
            #pragma unroll
            for (int nt = 0; nt < 2; nt++)
                #pragma unroll
                for (int i = 0; i < 4; i++)
                    xe[nt][i] = fmaf(dt, v[nt][i], xe[nt][i]);
        }

        #pragma unroll
        for (int nt = 0; nt < 2; nt++) {
            *(float2*)&out[(size_t)(row0 + g)     * 16 + 8 * nt + 2 * tg] =
                make_float2(xe[nt][0], xe[nt][1]);
            *(float2*)&out[(size_t)(row0 + g + 8) * 16 + 8 * nt + 2 * tg] =
                make_float2(xe[nt][2], xe[nt][3]);
        }
        if (tg == 0) {
            out[(size_t)batch * 16 + row0 + g]     = logq0;
            out[(size_t)batch * 16 + row0 + g + 8] = logq1;
        }
    }
}

extern "C" void kernel_launch(void* const* d_in, const int* in_sizes, int n_in,
                              void* d_out, int out_size) {
    const float* x0 = (const float*)d_in[0];
    const float* W1 = (const float*)d_in[1];
    const float* b1 = (const float*)d_in[2];
    const float* W2 = (const float*)d_in[3];
    const float* b2 = (const float*)d_in[4];
    float* out = (float*)d_out;

    const int batch = in_sizes[0] / 16;
    flow_kernel<<<GRID, THREADS>>>(x0, W1, b1, W2, b2, out, batch);
}

// round 17
// speedup vs baseline: 1.0892x; 1.0892x over previous
#include <cuda_runtime.h>
#include <math.h>
#include <stdint.h>

// Flow_49546742727298: CNF Euler, exact divergence via analytic trace.
// R17: R15 (fp16 MMA, zero relayout, 3 CTAs/SM persistent) plus:
//   - divergence Σ h²c computed ON THE TENSOR PIPE: h² via HMUL2 of the
//     already-packed ha frags, c as an all-columns-equal B-frag, 4 extra
//     MMAs with fp32 accumulate. Kills 32 FMUL + 32 FFMA + 8 SHFL per step.
//   - next-tile x prefetched into registers to hide tile-start LDG latency.

#define THREADS 128
#define NSTEPS  2
#define GRID    (3 * 148)

__device__ __forceinline__ uint32_t pack_f16x2(float lo, float hi) {
    uint32_t d; asm("cvt.rn.f16x2.f32 %0, %1, %2;" : "=r"(d) : "f"(hi), "f"(lo)); return d;
}
__device__ __forceinline__ uint32_t hmul2(uint32_t a, uint32_t b) {
    uint32_t d; asm("mul.rn.f16x2 %0, %1, %2;" : "=r"(d) : "r"(a), "r"(b)); return d;
}
__device__ __forceinline__ float fast_tanh(float x) {
    float y; asm("tanh.approx.f32 %0, %1;" : "=f"(y) : "f"(x)); return y;
}
__device__ __forceinline__ void mma_f16(float c[4], const uint32_t a[4],
                                        const uint32_t b0, const uint32_t b1) {
    asm("mma.sync.aligned.m16n8k16.row.col.f32.f16.f16.f32 "
        "{%0,%1,%2,%3}, {%4,%5,%6,%7}, {%8,%9}, {%0,%1,%2,%3};"
        : "+f"(c[0]), "+f"(c[1]), "+f"(c[2]), "+f"(c[3])
        : "r"(a[0]), "r"(a[1]), "r"(a[2]), "r"(a[3]), "r"(b0), "r"(b1));
}

__global__ void __launch_bounds__(THREADS, 3)
flow_kernel(const float* __restrict__ x0,
            const float* __restrict__ W1,
            const float* __restrict__ b1,
            const float* __restrict__ W2,
            const float* __restrict__ b2,
            float* __restrict__ out,
            int batch)
{
    __shared__ float sbias[2][64];
    __shared__ float scj[64];
    __shared__ __align__(8) float sb2s[16];

    const int tid  = threadIdx.x;
    const int lane = tid & 31;
    const int warp = tid >> 5;
    const int g    = lane >> 2;
    const int tg   = lane & 3;

    if (tid < 64) {
        const int j = tid;
        float c = 0.f;
        #pragma unroll
        for (int i = 0; i < 16; i++)
            c += W1[i * 64 + j] * W2[j * 16 + i];
        float bb = b1[j];
        float wt = W1[16 * 64 + j];
        scj[j] = c;
        sbias[0][j] = bb;
        sbias[1][j] = fmaf(0.5f, wt, bb);
    } else if (tid < 80) {
        sb2s[tid - 64] = b2[tid - 64];
    }
    __syncthreads();

    float csum;
    {
        float cpart = scj[lane] + scj[lane + 32];
        #pragma unroll
        for (int d = 16; d >= 1; d >>= 1)
            cpart += __shfl_xor_sync(0xffffffffu, cpart, d);
        csum = cpart;
    }

    // ---- persistent fp16 weight fragments ----
    uint32_t w1f[8][2];
    #pragma unroll
    for (int nt = 0; nt < 8; nt++) {
        int col = 8 * nt + g;
        w1f[nt][0] = pack_f16x2(W1[(2 * tg)     * 64 + col], W1[(2 * tg + 1) * 64 + col]);
        w1f[nt][1] = pack_f16x2(W1[(2 * tg + 8) * 64 + col], W1[(2 * tg + 9) * 64 + col]);
    }
    uint32_t w2f[4][2][2];
    #pragma unroll
    for (int kt = 0; kt < 4; kt++)
        #pragma unroll
        for (int nt = 0; nt < 2; nt++) {
            int col = 8 * nt + g;
            int k0 = 16 * kt + 2 * tg;
            w2f[kt][nt][0] = pack_f16x2(W2[k0       * 16 + col], W2[(k0 + 1) * 16 + col]);
            w2f[kt][nt][1] = pack_f16x2(W2[(k0 + 8) * 16 + col], W2[(k0 + 9) * 16 + col]);
        }
    // c_j as B-frag with all 8 columns identical (column index drops out):
    uint32_t cf[4][2];
    #pragma unroll
    for (int kt = 0; kt < 4; kt++) {
        int k0 = 16 * kt + 2 * tg;
        cf[kt][0] = pack_f16x2(scj[k0],     scj[k0 + 1]);
        cf[kt][1] = pack_f16x2(scj[k0 + 8], scj[k0 + 9]);
    }

    const float dt = 0.5f;
    const int gwarp  = blockIdx.x * 4 + warp;
    const int nwarps = GRID * 4;
    const int ntiles = batch >> 4;

    // ---- prefetch first tile's x ----
    float xn[2][4];
    if (gwarp < ntiles) {
        const int r0 = gwarp << 4;
        #pragma unroll
        for (int nt = 0; nt < 2; nt++) {
            float2 lo = *(const float2*)&x0[(size_t)(r0 + g)     * 16 + 8 * nt + 2 * tg];
            float2 hi = *(const float2*)&x0[(size_t)(r0 + g + 8) * 16 + 8 * nt + 2 * tg];
            xn[nt][0] = lo.x; xn[nt][1] = lo.y;
            xn[nt][2] = hi.x; xn[nt][3] = hi.y;
        }
    }

    for (int wt = gwarp; wt < ntiles; wt += nwarps) {
        const int row0 = wt << 4;

        // consume prefetched x; immediately issue next tile's loads
        float xe[2][4];
        #pragma unroll
        for (int nt = 0; nt < 2; nt++)
            #pragma unroll
            for (int i = 0; i < 4; i++)
                xe[nt][i] = xn[nt][i];
        const int wtn = wt + nwarps;
        if (wtn < ntiles) {
            const int r0 = wtn << 4;
            #pragma unroll
            for (int nt = 0; nt < 2; nt++) {
                float2 lo = *(const float2*)&x0[(size_t)(r0 + g)     * 16 + 8 * nt + 2 * tg];
                float2 hi = *(const float2*)&x0[(size_t)(r0 + g + 8) * 16 + 8 * nt + 2 * tg];
                xn[nt][0] = lo.x; xn[nt][1] = lo.y;
                xn[nt][2] = hi.x; xn[nt][3] = hi.y;
            }
        }

        float logq0 = 0.f, logq1 = 0.f;

        #pragma unroll
        for (int s = 0; s < NSTEPS; s++) {
            uint32_t xa[4];
            xa[0] = pack_f16x2(xe[0][0], xe[0][1]);
            xa[1] = pack_f16x2(xe[0][2], xe[0][3]);
            xa[2] = pack_f16x2(xe[1][0], xe[1][1]);
            xa[3] = pack_f16x2(xe[1][2], xe[1][3]);

            // GEMM1: h = x @ W1 + bse
            float h[8][4];
            #pragma unroll
            for (int nt = 0; nt < 8; nt++) {
                float2 bb = *(const float2*)&sbias[s][8 * nt + 2 * tg];
                h[nt][0] = bb.x; h[nt][1] = bb.y;
                h[nt][2] = bb.x; h[nt][3] = bb.y;
                mma_f16(h[nt], xa, w1f[nt][0], w1f[nt][1]);
            }

            // tanh, then pack straight to A-frags
            uint32_t ha[4][4];
            #pragma unroll
            for (int nt = 0; nt < 8; nt++) {
                h[nt][0] = fast_tanh(h[nt][0]);
                h[nt][1] = fast_tanh(h[nt][1]);
                h[nt][2] = fast_tanh(h[nt][2]);
                h[nt][3] = fast_tanh(h[nt][3]);
            }
            #pragma unroll
            for (int kt = 0; kt < 4; kt++) {
                ha[kt][0] = pack_f16x2(h[2 * kt][0],     h[2 * kt][1]);
                ha[kt][1] = pack_f16x2(h[2 * kt][2],     h[2 * kt][3]);
                ha[kt][2] = pack_f16x2(h[2 * kt + 1][0], h[2 * kt + 1][1]);
                ha[kt][3] = pack_f16x2(h[2 * kt + 1][2], h[2 * kt + 1][3]);
            }

            // divergence on the tensor pipe: d = (h.*h) @ c (all cols equal)
            float dacc[4] = {0.f, 0.f, 0.f, 0.f};
            #pragma unroll
            for (int kt = 0; kt < 4; kt++) {
                uint32_t hha[4];
                hha[0] = hmul2(ha[kt][0], ha[kt][0]);
                hha[1] = hmul2(ha[kt][1], ha[kt][1]);
                hha[2] = hmul2(ha[kt][2], ha[kt][2]);
                hha[3] = hmul2(ha[kt][3], ha[kt][3]);
                mma_f16(dacc, hha, cf[kt][0], cf[kt][1]);
            }
            logq0 -= dt * (csum - dacc[0]);   // row g   (all cols identical)
            logq1 -= dt * (csum - dacc[2]);   // row g+8

            // GEMM2: v = h @ W2 + b2
            float v[2][4];
            #pragma unroll
            for (int nt = 0; nt < 2; nt++) {
                float2 bb = *(const float2*)&sb2s[8 * nt + 2 * tg];
                float va[4] = {bb.x, bb.y, bb.x, bb.y};
                float vb[4] = {0.f, 0.f, 0.f, 0.f};
                mma_f16(va, ha[0], w2f[0][nt][0], w2f[0][nt][1]);
                mma_f16(vb, ha[1], w2f[1][nt][0], w2f[1][nt][1]);
                mma_f16(va, ha[2], w2f[2][nt][0], w2f[2][nt][1]);
                mma_f16(vb, ha[3], w2f[3][nt][0], w2f[3][nt][1]);
                #pragma unroll
                for (int i = 0; i < 4; i++) v[nt][i] = va[i] + vb[i];
            }

            // exact-fp32 x update (v C-frag == x layout)
            #pragma unroll
            for (int nt = 0; nt < 2; nt++)
                #pragma unroll
                for (int i = 0; i < 4; i++)
                    xe[nt][i] = fmaf(dt, v[nt][i], xe[nt][i]);
        }

        #pragma unroll
        for (int nt = 0; nt < 2; nt++) {
            *(float2*)&out[(size_t)(row0 + g)     * 16 + 8 * nt + 2 * tg] =
                make_float2(xe[nt][0], xe[nt][1]);
            *(float2*)&out[(size_t)(row0 + g + 8) * 16 + 8 * nt + 2 * tg] =
                make_float2(xe[nt][2], xe[nt][3]);
        }
        if (tg == 0) {
            out[(size_t)batch * 16 + row0 + g]     = logq0;
            out[(size_t)batch * 16 + row0 + g + 8] = logq1;
        }
    }
}

extern "C" void kernel_launch(void* const* d_in, const int* in_sizes, int n_in,
                              void* d_out, int out_size) {
    const float* x0 = (const float*)d_in[0];
    const float* W1 = (const float*)d_in[1];
    const float* b1 = (const float*)d_in[2];
    const float* W2 = (const float*)d_in[3];
    const float* b2 = (const float*)d_in[4];
    float* out = (float*)d_out;

    const int batch = in_sizes[0] / 16;
    flow_kernel<<<GRID, THREADS>>>(x0, W1, b1, W2, b2, out, batch);
}